// round 14
// baseline (speedup 1.0000x reference)
#include <cuda_runtime.h>

// CARAFE: features [2,64,64,256] f32, masks [2,128,128,25] f32, k=5, group=1.
// Nearest 64->128 half-pixel => src = dst >> 1.
// R14: dual-stream. Each thread processes TWO adjacent source pixels at once:
//      per (d,r) step 2 independent LDS.128 feed 16 FFMA across 16 independent
//      accumulators (intra-warp MLP-2). Shared 5x6 rotating window (2 refill
//      cols per pair-step). R10 staging + d-major + immediate offsets +
//      interior/border split retained.

#define FH 64
#define FW 64
#define C2 128     // 256 channels / 2 (float2 groups)
#define OH 128
#define OW 128
#define KK 25
#define SEGW 8
#define NS 6       // window slots (6 live columns for a pixel pair)

__device__ __forceinline__ void fma2s(float2& a, const float2 f, const float m) {
    a.x = fmaf(f.x, m, a.x);
    a.y = fmaf(f.y, m, a.y);
}

template<bool CHK>
__device__ __forceinline__ void carafe_body(int seg, int hs, int b,
                                            const float2* __restrict__ F,
                                            float2* __restrict__ O,
                                            const float* __restrict__ smask,
                                            int c2)
{
    const int ws0 = seg * SEGW;
    const float2 z = make_float2(0.f, 0.f);

    // feature base at (row hs-2, col ws0-2); local col c = global - (ws0-2).
    const float2* fb = F + ((b * FH + (hs - 2)) * FW + (ws0 - 2)) * C2 + c2;

    bool rok[5];
    #pragma unroll
    for (int r = 0; r < 5; r++) {
        int hr = hs - 2 + r;
        rok[r] = CHK ? (hr >= 0 && hr < FH) : true;
    }

    // 6-slot rotating window, slot(c) = c % 6. Init: local cols 0..5.
    float2 w[5][NS];
    #pragma unroll
    for (int c = 0; c < 6; c++) {
        bool cok = CHK ? ((ws0 - 2 + c) >= 0 && (ws0 - 2 + c) < FW) : true;
        #pragma unroll
        for (int r = 0; r < 5; r++)
            w[r][c % NS] = (rok[r] && cok) ? fb[(r * FW + c) * C2] : z;
    }

    float2* ob = O + ((b * OH + 2 * hs) * OW + 2 * ws0) * C2 + c2;

    #pragma unroll
    for (int t = 0; t < SEGW / 2; t++) {
        // pixel pair P0 = ws0+2t, P1 = ws0+2t+1
        const float4* __restrict__ mp0 =
            (const float4*)(smask + (2 * t) * (KK * 4));
        const float4* __restrict__ mp1 =
            (const float4*)(smask + (2 * t + 1) * (KK * 4));

        float2 a0 = z, a1 = z, a2 = z, a3 = z;   // P0 accumulators
        float2 b0 = z, b1 = z, b2 = z, b3 = z;   // P1 accumulators

        // d-major sweep, two interleaved independent streams.
        // P0 tap (d,r): local col 2t+d -> slot (2t+d)%6; P1: (2t+d+1)%6.
        #pragma unroll
        for (int d = 0; d < 5; d++) {
            #pragma unroll
            for (int r = 0; r < 5; r++) {
                const float2 f0 = w[r][(2 * t + d) % NS];
                const float2 f1 = w[r][(2 * t + d + 1) % NS];
                const float4 m0 = mp0[r * 5 + d];   // LDS.128 broadcast, stream A
                const float4 m1 = mp1[r * 5 + d];   // LDS.128 broadcast, stream B
                fma2s(a0, f0, m0.x);  fma2s(b0, f1, m1.x);
                fma2s(a1, f0, m0.y);  fma2s(b1, f1, m1.y);
                fma2s(a2, f0, m0.z);  fma2s(b2, f1, m1.z);
                fma2s(a3, f0, m0.w);  fma2s(b3, f1, m1.w);
            }
        }

        // stores: P0 -> out cols 4t,4t+1; P1 -> 4t+2,4t+3 (both output rows)
        ob[(4 * t) * C2]              = a0;
        ob[(4 * t + 1) * C2]          = a1;
        ob[(OW + 4 * t) * C2]         = a2;
        ob[(OW + 4 * t + 1) * C2]     = a3;
        ob[(4 * t + 2) * C2]          = b0;
        ob[(4 * t + 3) * C2]          = b1;
        ob[(OW + 4 * t + 2) * C2]     = b2;
        ob[(OW + 4 * t + 3) * C2]     = b3;

        if (t < SEGW / 2 - 1) {
            // refill local cols 2t+6, 2t+7 into slots (2t)%6, (2t+1)%6 (dead).
            #pragma unroll
            for (int j = 0; j < 2; j++) {
                const int c = 2 * t + 6 + j;
                const bool cok = CHK ? ((ws0 - 2 + c) < FW) : true;
                #pragma unroll
                for (int r = 0; r < 5; r++)
                    w[r][c % NS] = (rok[r] && cok) ? fb[(r * FW + c) * C2] : z;
            }
        }
    }
}

__global__ __launch_bounds__(128)
void carafe_kernel(const float* __restrict__ features,
                   const float* __restrict__ masks,
                   float* __restrict__ out)
{
    // smask layout: [px(8)][p(25)][out(4)], p = r*5+d (source order)
    __shared__ __align__(16) float smask[SEGW * KK * 4];

    const int tid = threadIdx.x;
    const int seg = blockIdx.x;
    const int hs  = blockIdx.y;
    const int b   = blockIdx.z;
    const int ws0 = seg * SEGW;

    // ---- division-free mask transpose stage (R10) ----
    // tid = px*16 + o*4 + q; thread copies taps p = q+4k, immediate offsets.
    {
        const int q  = tid & 3;
        const int o  = (tid >> 2) & 3;
        const int px = tid >> 4;
        const int oy = o >> 1;
        const int ox = o & 1;

        const float* gm = masks
            + ((b * OH + 2 * hs + oy) * OW + 2 * (ws0 + px) + ox) * KK + q;
        float* sm = smask + px * (KK * 4) + q * 4 + o;

        #pragma unroll
        for (int k = 0; k < 7; k++) {
            if (k < 6 || q == 0)
                sm[k * 16] = gm[k * 4];
        }
    }
    __syncthreads();

    const float2* F = (const float2*)features;
    float2* O = (float2*)out;

    const bool interior = (seg >= 1) && (seg <= 6) && (hs >= 2) && (hs <= 61);
    if (interior)
        carafe_body<false>(seg, hs, b, F, O, smask, tid);
    else
        carafe_body<true>(seg, hs, b, F, O, smask, tid);
}

extern "C" void kernel_launch(void* const* d_in, const int* in_sizes, int n_in,
                              void* d_out, int out_size) {
    const float* features = (const float*)d_in[0];
    const float* masks    = (const float*)d_in[1];
    float* out            = (float*)d_out;

    dim3 grid(FW / SEGW, FH, 2);   // (8, 64, 2) = 1024 blocks x 4 warps
    carafe_kernel<<<grid, 128>>>(features, masks, out);
}

// round 15
// speedup vs baseline: 1.0896x; 1.0896x over previous
#include <cuda_runtime.h>

// CARAFE: features [2,64,64,256] f32, masks [2,128,128,25] f32, k=5, group=1.
// Nearest 64->128 half-pixel => src = dst >> 1.
// R15: R10/R13 config + prologue overlap: the 25 initial window LDGs are
//      issued BEFORE mask staging + __syncthreads, so window-fill latency
//      retires underneath the staging loads and barrier (~400 serialized
//      cycles per block generation reclaimed). Body unchanged: float2 5-slot
//      rotating window, d-major taps, immediate offsets, interior/border split.

#define FH 64
#define FW 64
#define C2 128     // 256 channels / 2 (float2 groups)
#define OH 128
#define OW 128
#define KK 25
#define SEGW 8

__device__ __forceinline__ void fma2s(float2& a, const float2 f, const float m) {
    a.x = fmaf(f.x, m, a.x);
    a.y = fmaf(f.y, m, a.y);
}

template<bool CHK>
__device__ __forceinline__ void win_fill(float2 (&w)[5][5],
                                         const float2* __restrict__ fb,
                                         const bool (&rok)[5], int ws0)
{
    const float2 z = make_float2(0.f, 0.f);
    #pragma unroll
    for (int j = 0; j < 5; j++) {
        bool cok = CHK ? ((ws0 - 2 + j) >= 0 && (ws0 - 2 + j) < FW) : true;
        #pragma unroll
        for (int r = 0; r < 5; r++)
            w[r][j] = (rok[r] && cok) ? fb[(r * FW + j) * C2] : z;
    }
}

template<bool CHK>
__device__ __forceinline__ void carafe_compute(float2 (&w)[5][5],
                                               const float2* __restrict__ fb,
                                               const bool (&rok)[5], int ws0,
                                               float2* __restrict__ ob,
                                               const float* __restrict__ smask)
{
    const float2 z = make_float2(0.f, 0.f);

    #pragma unroll
    for (int s = 0; s < SEGW; s++) {
        // smask pixel s, source tap order p = r*5+d, float4 = 4 outputs' masks
        const float4* __restrict__ mp = (const float4*)(smask + s * (KK * 4));

        float2 a0 = z, a1 = z, a2 = z, a3 = z;

        // d-major sweep: slot refilled at end of iter s-1 consumed only at d=4
        #pragma unroll
        for (int d = 0; d < 5; d++) {
            #pragma unroll
            for (int r = 0; r < 5; r++) {
                const float2 f = w[r][(s + d) % 5];   // compile-time slot
                const float4 m = mp[r * 5 + d];       // broadcast LDS.128
                fma2s(a0, f, m.x);
                fma2s(a1, f, m.y);
                fma2s(a2, f, m.z);
                fma2s(a3, f, m.w);
            }
        }

        ob[(2 * s) * C2]          = a0;
        ob[(2 * s + 1) * C2]      = a1;
        ob[(OW + 2 * s) * C2]     = a2;
        ob[(OW + 2 * s + 1) * C2] = a3;

        if (s < SEGW - 1) {
            const bool cok = CHK ? ((ws0 + s + 3) < FW) : true;
            #pragma unroll
            for (int r = 0; r < 5; r++)
                w[r][s % 5] = (rok[r] && cok) ? fb[(r * FW + (s + 5)) * C2] : z;
        }
    }
}

__global__ __launch_bounds__(128)
void carafe_kernel(const float* __restrict__ features,
                   const float* __restrict__ masks,
                   float* __restrict__ out)
{
    // smask layout: [px(8)][p(25)][out(4)], p = r*5+d (source order)
    __shared__ __align__(16) float smask[SEGW * KK * 4];

    const int tid = threadIdx.x;
    const int seg = blockIdx.x;
    const int hs  = blockIdx.y;
    const int b   = blockIdx.z;
    const int ws0 = seg * SEGW;

    const float2* F = (const float2*)features;
    float2* O = (float2*)out;

    const bool interior = (seg >= 1) && (seg <= 6) && (hs >= 2) && (hs <= 61);

    // ---- per-thread feature setup + window fill FIRST (register-destined,
    //      no smem dependency): 25 LDGs in flight before staging/barrier ----
    const float2* fb = F + ((b * FH + (hs - 2)) * FW + (ws0 - 2)) * C2 + tid;

    bool rok[5];
    #pragma unroll
    for (int r = 0; r < 5; r++) {
        int hr = hs - 2 + r;
        rok[r] = interior ? true : (hr >= 0 && hr < FH);
    }

    float2 w[5][5];
    if (interior)
        win_fill<false>(w, fb, rok, ws0);
    else
        win_fill<true>(w, fb, rok, ws0);

    // ---- division-free mask transpose stage (overlaps window LDG latency) ----
    // tid = px*16 + o*4 + q; thread copies taps p = q+4k, immediate offsets.
    {
        const int q  = tid & 3;
        const int o  = (tid >> 2) & 3;
        const int px = tid >> 4;
        const int oy = o >> 1;
        const int ox = o & 1;

        const float* gm = masks
            + ((b * OH + 2 * hs + oy) * OW + 2 * (ws0 + px) + ox) * KK + q;
        float* sm = smask + px * (KK * 4) + q * 4 + o;

        #pragma unroll
        for (int k = 0; k < 7; k++) {
            if (k < 6 || q == 0)
                sm[k * 16] = gm[k * 4];
        }
    }
    __syncthreads();

    float2* ob = O + ((b * OH + 2 * hs) * OW + 2 * ws0) * C2 + tid;

    if (interior)
        carafe_compute<false>(w, fb, rok, ws0, ob, smask);
    else
        carafe_compute<true>(w, fb, rok, ws0, ob, smask);
}

extern "C" void kernel_launch(void* const* d_in, const int* in_sizes, int n_in,
                              void* d_out, int out_size) {
    const float* features = (const float*)d_in[0];
    const float* masks    = (const float*)d_in[1];
    float* out            = (float*)d_out;

    dim3 grid(FW / SEGW, FH, 2);   // (8, 64, 2) = 1024 blocks x 4 warps
    carafe_kernel<<<grid, 128>>>(features, masks, out);
}

// round 16
// speedup vs baseline: 1.1364x; 1.0430x over previous
#include <cuda_runtime.h>

// CARAFE: features [2,64,64,256] f32, masks [2,128,128,25] f32, k=5, group=1.
// Nearest 64->128 half-pixel => src = dst >> 1.
// R16: two source ROWS per block (vertical patch reuse: rows share 4/5 window
//      rows). 6-row x 5-slot rotating float2 window; each (d,r) step feeds two
//      independent pixel streams (16 FFMA / 2 LDS.128). 2x FFMA per block
//      against the same prologue; 512 blocks = single balanced wave.

#define FH 64
#define FW 64
#define C2 128     // 256 channels / 2 (float2 groups)
#define OH 128
#define OW 128
#define KK 25
#define SEGW 8

__device__ __forceinline__ void fma2s(float2& a, const float2 f, const float m) {
    a.x = fmaf(f.x, m, a.x);
    a.y = fmaf(f.y, m, a.y);
}

template<bool CHK>
__device__ __forceinline__ void carafe_body(int seg, int hs0, int b,
                                            const float2* __restrict__ F,
                                            float2* __restrict__ O,
                                            const float* __restrict__ smask,
                                            int c2)
{
    const int ws0 = seg * SEGW;
    const float2 z = make_float2(0.f, 0.f);

    // feature base at (row hs0-2, col ws0-2); all accesses immediate offsets.
    const float2* fb = F + ((b * FH + (hs0 - 2)) * FW + (ws0 - 2)) * C2 + c2;

    bool rok[6];
    #pragma unroll
    for (int r = 0; r < 6; r++) {
        int hr = hs0 - 2 + r;
        rok[r] = CHK ? (hr >= 0 && hr < FH) : true;
    }

    // 6-row x 5-slot rotating window: col (ws0-2+j) -> slot j (mod 5)
    float2 w[6][5];
    #pragma unroll
    for (int j = 0; j < 5; j++) {
        bool cok = CHK ? ((ws0 - 2 + j) >= 0 && (ws0 - 2 + j) < FW) : true;
        #pragma unroll
        for (int r = 0; r < 6; r++)
            w[r][j] = (rok[r] && cok) ? fb[(r * FW + j) * C2] : z;
    }

    float2* ob = O + ((b * OH + 2 * hs0) * OW + 2 * ws0) * C2 + c2;

    #pragma unroll
    for (int s = 0; s < SEGW; s++) {
        // masks: [row2][px8][tap25][out4], source tap order p = r*5+d
        const float4* __restrict__ mp0 = (const float4*)(smask + s * (KK * 4));
        const float4* __restrict__ mp1 =
            (const float4*)(smask + (SEGW + s) * (KK * 4));

        float2 a0 = z, a1 = z, a2 = z, a3 = z;   // source row hs0
        float2 b0 = z, b1 = z, b2 = z, b3 = z;   // source row hs0+1

        // d-major sweep; two pixel streams share window registers (row r vs r+1)
        #pragma unroll
        for (int d = 0; d < 5; d++) {
            #pragma unroll
            for (int r = 0; r < 5; r++) {
                const int sl = (s + d) % 5;       // compile-time slot
                const float2 f0 = w[r][sl];
                const float2 f1 = w[r + 1][sl];
                const float4 m0 = mp0[r * 5 + d]; // LDS.128 broadcast, stream A
                const float4 m1 = mp1[r * 5 + d]; // LDS.128 broadcast, stream B
                fma2s(a0, f0, m0.x);  fma2s(b0, f1, m1.x);
                fma2s(a1, f0, m0.y);  fma2s(b1, f1, m1.y);
                fma2s(a2, f0, m0.z);  fma2s(b2, f1, m1.z);
                fma2s(a3, f0, m0.w);  fma2s(b3, f1, m1.w);
            }
        }

        ob[(2 * s) * C2]              = a0;   // out row 2*hs0
        ob[(2 * s + 1) * C2]          = a1;
        ob[(OW + 2 * s) * C2]         = a2;   // out row 2*hs0+1
        ob[(OW + 2 * s + 1) * C2]     = a3;
        ob[(2 * OW + 2 * s) * C2]     = b0;   // out row 2*hs0+2
        ob[(2 * OW + 2 * s + 1) * C2] = b1;
        ob[(3 * OW + 2 * s) * C2]     = b2;   // out row 2*hs0+3
        ob[(3 * OW + 2 * s + 1) * C2] = b3;

        if (s < SEGW - 1) {
            // refill col (ws0+s+3) into slot s%5; consumed at iter s+1, d=4
            const bool cok = CHK ? ((ws0 + s + 3) < FW) : true;
            #pragma unroll
            for (int r = 0; r < 6; r++)
                w[r][s % 5] = (rok[r] && cok) ? fb[(r * FW + (s + 5)) * C2] : z;
        }
    }
}

__global__ __launch_bounds__(128)
void carafe_kernel(const float* __restrict__ features,
                   const float* __restrict__ masks,
                   float* __restrict__ out)
{
    // smask: [srcrow(2)][px(8)][p(25)][out(4)], p = r*5+d (source order)
    __shared__ __align__(16) float smask[2 * SEGW * KK * 4];

    const int tid = threadIdx.x;
    const int seg = blockIdx.x;
    const int hs0 = blockIdx.y * 2;
    const int b   = blockIdx.z;
    const int ws0 = seg * SEGW;

    // ---- division-free mask transpose stage (R10), run twice (2 src rows) ----
    // tid = px*16 + o*4 + q; thread copies taps p = q+4k, immediate offsets.
    {
        const int q  = tid & 3;
        const int o  = (tid >> 2) & 3;
        const int px = tid >> 4;
        const int oy = o >> 1;
        const int ox = o & 1;

        #pragma unroll
        for (int row = 0; row < 2; row++) {
            const float* gm = masks
                + ((b * OH + 2 * hs0 + 2 * row + oy) * OW
                   + 2 * (ws0 + px) + ox) * KK + q;
            float* sm = smask + row * (SEGW * KK * 4) + px * (KK * 4) + q * 4 + o;
            #pragma unroll
            for (int k = 0; k < 7; k++) {
                if (k < 6 || q == 0)
                    sm[k * 16] = gm[k * 4];
            }
        }
    }
    __syncthreads();

    const float2* F = (const float2*)features;
    float2* O = (float2*)out;

    // interior: window rows hs0-2 .. hs0+3 all valid, cols ws0-2..ws0+10 valid
    const bool interior = (seg >= 1) && (seg <= 6) && (hs0 >= 2) && (hs0 <= 60);
    if (interior)
        carafe_body<false>(seg, hs0, b, F, O, smask, tid);
    else
        carafe_body<true>(seg, hs0, b, F, O, smask, tid);
}

extern "C" void kernel_launch(void* const* d_in, const int* in_sizes, int n_in,
                              void* d_out, int out_size) {
    const float* features = (const float*)d_in[0];
    const float* masks    = (const float*)d_in[1];
    float* out            = (float*)d_out;

    dim3 grid(FW / SEGW, FH / 2, 2);   // (8, 32, 2) = 512 blocks x 4 warps
    carafe_kernel<<<grid, 128>>>(features, masks, out);
}